// round 4
// baseline (speedup 1.0000x reference)
#include <cuda_runtime.h>
#include <cuda_bf16.h>
#include <cstdint>

// Problem constants (fixed shapes for this registry entry)
#define MAX_N 100000
#define MAX_T 3
#define D 128   // D_IN == D_OUT == 128

// Scratch (allocation-free rule: __device__ globals)
__device__ float g_xw[(size_t)MAX_T * MAX_N * D];   // 153.6 MB
__device__ int   g_dcnt[MAX_T * MAX_N];
__device__ float g_dis[MAX_T * MAX_N];

// ---------------------------------------------------------------------------
// 1) zero degree counters
__global__ void k_deg_zero(int* dcnt, int n) {
    int i = blockIdx.x * blockDim.x + threadIdx.x;
    if (i < n) dcnt[i] = 0;
}

// 2) count incoming edges per (relation, dst)
__global__ void k_deg_count(const int* __restrict__ edges, int* __restrict__ dcnt,
                            int N, int E, int T) {
    int i = blockIdx.x * blockDim.x + threadIdx.x;
    int total = T * E;
    if (i >= total) return;
    int t = i / E;
    int e = i - t * E;
    int d = __ldg(edges + (size_t)t * 2 * E + E + e);   // dst
    atomicAdd(dcnt + t * N + d, 1);
}

// 3) dis = rsqrt(count + 1)   (+1 = self loop; always > 0)
__global__ void k_dis(const int* __restrict__ dcnt, float* __restrict__ dis, int n) {
    int i = blockIdx.x * blockDim.x + threadIdx.x;
    if (i < n) dis[i] = rsqrtf((float)(dcnt[i] + 1));
}

// ---------------------------------------------------------------------------
// 4) xw[t] = x @ W[t]    fp32 tiled GEMM
//    block = 256 threads, tile = 64 rows x 128 cols, K split into 2 halves.
__global__ void k_gemm_xw(const float* __restrict__ x, const float* __restrict__ W,
                          float* __restrict__ xw, int N) {
    __shared__ float Ws[64 * 128];   // 32 KB (one K-half of W)
    __shared__ float Xs[64 * 64];    // 16 KB (64 rows x 64 k)

    const int t  = blockIdx.y;
    const int m0 = blockIdx.x * 64;
    const float* Wt = W + (size_t)t * D * D;

    const int tid = threadIdx.x;
    const int tx = tid & 31;
    const int ty = tid >> 5;

    float4 acc[8];
#pragma unroll
    for (int r = 0; r < 8; r++) acc[r] = make_float4(0.f, 0.f, 0.f, 0.f);

    for (int kh = 0; kh < 2; kh++) {
        // load W half: rows kh*64..+64, all 128 cols  (2048 float4)
        for (int i = tid; i < 64 * 32; i += 256) {
            int kk = i >> 5, c4 = i & 31;
            ((float4*)Ws)[i] = ((const float4*)(Wt + (size_t)(kh * 64 + kk) * D))[c4];
        }
        // load X tile: rows m0..m0+63, cols kh*64..+64  (1024 float4)
        for (int i = tid; i < 64 * 16; i += 256) {
            int r = i >> 4, c4 = i & 15;
            float4 v = make_float4(0.f, 0.f, 0.f, 0.f);
            if (m0 + r < N)
                v = ((const float4*)(x + (size_t)(m0 + r) * D + kh * 64))[c4];
            ((float4*)Xs)[r * 16 + c4] = v;
        }
        __syncthreads();

#pragma unroll 8
        for (int k = 0; k < 64; k++) {
            float4 w = ((const float4*)Ws)[k * 32 + tx];
#pragma unroll
            for (int r = 0; r < 8; r++) {
                float xv = Xs[(ty + 8 * r) * 64 + k];   // warp-broadcast
                acc[r].x += xv * w.x;
                acc[r].y += xv * w.y;
                acc[r].z += xv * w.z;
                acc[r].w += xv * w.w;
            }
        }
        __syncthreads();
    }

#pragma unroll
    for (int r = 0; r < 8; r++) {
        int row = m0 + ty + 8 * r;
        if (row < N)
            ((float4*)(xw + ((size_t)t * N + row) * D))[tx] = acc[r];
    }
}

// ---------------------------------------------------------------------------
// 5) out[n] = sum_t ( xw[t][n] * dis[t][n]^2 + b[t] )   (self-loop + biases)
//    Fully overwrites the poisoned output buffer.
__global__ void k_init_out(const float* __restrict__ xw, const float* __restrict__ dis,
                           const float* __restrict__ b, float* __restrict__ out,
                           int N, int T) {
    int i = blockIdx.x * blockDim.x + threadIdx.x;   // over N * 32 float4
    if (i >= N * 32) return;
    int n  = i >> 5;
    int c4 = i & 31;
    float4 acc = make_float4(0.f, 0.f, 0.f, 0.f);
    for (int t = 0; t < T; t++) {
        float ds = __ldg(dis + t * N + n);
        float d2 = ds * ds;
        float4 v  = __ldg((const float4*)(xw + ((size_t)t * N + n) * D) + c4);
        float4 bb = __ldg((const float4*)(b + (size_t)t * D) + c4);
        acc.x += v.x * d2 + bb.x;
        acc.y += v.y * d2 + bb.y;
        acc.z += v.z * d2 + bb.z;
        acc.w += v.w * d2 + bb.w;
    }
    ((float4*)out)[i] = acc;
}

// ---------------------------------------------------------------------------
// 6) per-edge gather + scatter-add. One warp per edge; lane handles 4 cols.
//    Vector reduction: one red.global.add.v4.f32 per lane (sm_90+).
__global__ void k_scatter(const float* __restrict__ xw, const float* __restrict__ dis,
                          const int* __restrict__ edges, float* __restrict__ out,
                          int N, int E, int T) {
    int gw   = (blockIdx.x * blockDim.x + threadIdx.x) >> 5;   // global warp = edge slot
    int lane = threadIdx.x & 31;
    int total = T * E;
    if (gw >= total) return;
    int t = gw / E;
    int e = gw - t * E;
    const int* srcp = edges + (size_t)t * 2 * E;
    const int* dstp = srcp + E;
    int s = __ldg(srcp + e);
    int d = __ldg(dstp + e);
    float norm = __ldg(dis + t * N + s) * __ldg(dis + t * N + d);
    float4 v = __ldg((const float4*)(xw + ((size_t)t * N + s) * D) + lane);
    float* o = out + (size_t)d * D + lane * 4;
#if __CUDA_ARCH__ >= 900
    asm volatile("red.global.add.v4.f32 [%0], {%1, %2, %3, %4};"
                 :: "l"(o), "f"(v.x * norm), "f"(v.y * norm),
                    "f"(v.z * norm), "f"(v.w * norm)
                 : "memory");
#else
    atomicAdd(o + 0, v.x * norm);
    atomicAdd(o + 1, v.y * norm);
    atomicAdd(o + 2, v.z * norm);
    atomicAdd(o + 3, v.w * norm);
#endif
}

// ---------------------------------------------------------------------------
extern "C" void kernel_launch(void* const* d_in, const int* in_sizes, int n_in,
                              void* d_out, int out_size) {
    const float* x     = (const float*)d_in[0];   // [N, 128]
    const int*   edges = (const int*)d_in[1];     // [T, 2, E]
    const float* W     = (const float*)d_in[2];   // [T, 128, 128]
    const float* b     = (const float*)d_in[3];   // [T, 128]
    float* out = (float*)d_out;                   // [N, 128]

    const int N = in_sizes[0] / D;
    const int T = in_sizes[3] / D;
    const int E = in_sizes[1] / (2 * T);

    float* xw   = nullptr;
    int*   dcnt = nullptr;
    float* dis  = nullptr;
    cudaGetSymbolAddress((void**)(&xw),   g_xw);
    cudaGetSymbolAddress((void**)(&dcnt), g_dcnt);
    cudaGetSymbolAddress((void**)(&dis),  g_dis);

    // 1) zero degree counters
    {
        int n = T * N;
        k_deg_zero<<<(n + 255) / 256, 256>>>(dcnt, n);
    }
    // 2) count
    {
        int total = T * E;
        k_deg_count<<<(total + 255) / 256, 256>>>(edges, dcnt, N, E, T);
    }
    // 3) dis
    {
        int n = T * N;
        k_dis<<<(n + 255) / 256, 256>>>(dcnt, dis, n);
    }
    // 4) GEMM xw[t] = x @ W[t]
    {
        dim3 grid((N + 63) / 64, T);
        k_gemm_xw<<<grid, 256>>>(x, W, xw, N);
    }
    // 5) init out with self-loop + bias
    {
        int n = N * 32;
        k_init_out<<<(n + 255) / 256, 256>>>(xw, dis, b, out, N, T);
    }
    // 6) edge scatter (8 warps / block of 256)
    {
        int total = T * E;
        int blocks = (total + 7) / 8;
        k_scatter<<<blocks, 256>>>(xw, dis, edges, out, N, E, T);
    }
}

// round 7
// speedup vs baseline: 1.0061x; 1.0061x over previous
#include <cuda_runtime.h>
#include <cuda_bf16.h>
#include <cstdint>

// Fixed shapes for this registry entry
#define MAX_N 100000
#define MAX_T 3
#define D 128   // D_IN == D_OUT == 128

// Scratch (allocation-free rule: __device__ globals)
__device__ float g_agg[(size_t)MAX_T * MAX_N * D];   // 153.6 MB aggregated features
__device__ int   g_dcnt[MAX_T * MAX_N];
__device__ float g_dis[MAX_T * MAX_N];

// ---------------------------------------------------------------------------
// 1) zero degree counters
__global__ void k_deg_zero(int* dcnt, int n) {
    int i = blockIdx.x * blockDim.x + threadIdx.x;
    if (i < n) dcnt[i] = 0;
}

// 2) count incoming edges per (relation, dst)
__global__ void k_deg_count(const int* __restrict__ edges, int* __restrict__ dcnt,
                            int N, int E, int T) {
    int i = blockIdx.x * blockDim.x + threadIdx.x;
    int total = T * E;
    if (i >= total) return;
    int t = i / E;
    int e = i - t * E;
    int d = __ldg(edges + (size_t)t * 2 * E + E + e);   // dst
    atomicAdd(dcnt + t * N + d, 1);
}

// 3) dis = rsqrt(count + 1)   (+1 = self loop; always > 0)
__global__ void k_dis(const int* __restrict__ dcnt, float* __restrict__ dis, int n) {
    int i = blockIdx.x * blockDim.x + threadIdx.x;
    if (i < n) dis[i] = rsqrtf((float)(dcnt[i] + 1));
}

// ---------------------------------------------------------------------------
// 4) agg[t][n] = dis[t][n]^2 * x[n]    (self-loop term; also the zero-init)
__global__ void k_agg_init(const float* __restrict__ x, const float* __restrict__ dis,
                           float* __restrict__ agg, int N, int T) {
    int i = blockIdx.x * blockDim.x + threadIdx.x;   // over T * N * 32 float4
    int n32 = N * 32;
    if (i >= T * n32) return;
    int t   = i / n32;
    int rem = i - t * n32;
    int n   = rem >> 5;
    int c4  = rem & 31;
    float ds = __ldg(dis + t * N + n);
    float d2 = ds * ds;
    float4 v = __ldg((const float4*)x + (size_t)n * 32 + c4);
    v.x *= d2; v.y *= d2; v.z *= d2; v.w *= d2;
    ((float4*)agg)[(size_t)i] = v;
}

// ---------------------------------------------------------------------------
// 5) per-edge gather (from x, L2-resident) + scatter-add into agg[t].
//    One warp per edge; lane handles 4 cols; one red.global.add.v4.f32 per lane.
__global__ void k_scatter(const float* __restrict__ x, const float* __restrict__ dis,
                          const int* __restrict__ edges, float* __restrict__ agg,
                          int N, int E, int T) {
    int gw   = (blockIdx.x * blockDim.x + threadIdx.x) >> 5;   // edge slot
    int lane = threadIdx.x & 31;
    int total = T * E;
    if (gw >= total) return;
    int t = gw / E;
    int e = gw - t * E;
    const int* srcp = edges + (size_t)t * 2 * E;
    const int* dstp = srcp + E;
    int s = __ldg(srcp + e);
    int d = __ldg(dstp + e);
    float norm = __ldg(dis + t * N + s) * __ldg(dis + t * N + d);
    float4 v = __ldg((const float4*)x + (size_t)s * 32 + lane);
    float* o = agg + ((size_t)t * N + d) * D + lane * 4;
    asm volatile("red.global.add.v4.f32 [%0], {%1, %2, %3, %4};"
                 :: "l"(o), "f"(v.x * norm), "f"(v.y * norm),
                    "f"(v.z * norm), "f"(v.w * norm)
                 : "memory");
}

// ---------------------------------------------------------------------------
// 6) out = sum_t agg[t] @ W[t] + sum_t b[t]
//    block = 256 threads, tile = 64 rows x 128 cols; t-loop and K-halves fused.
//    Inner loop vectorized over k (float4) on both operands.
__global__ void __launch_bounds__(256, 3)
k_gemm_out(const float* __restrict__ agg, const float* __restrict__ W,
           const float* __restrict__ b, float* __restrict__ out, int N, int T) {
    __shared__ float Ws[64 * 128];   // 32 KB (one K-half of W_t)
    __shared__ float Xs[64 * 64];    // 16 KB (64 rows x 64 k of agg_t)

    const int m0  = blockIdx.x * 64;
    const int tid = threadIdx.x;
    const int tx  = tid & 31;
    const int ty  = tid >> 5;

    float4 acc[8];
#pragma unroll
    for (int r = 0; r < 8; r++) acc[r] = make_float4(0.f, 0.f, 0.f, 0.f);

    for (int t = 0; t < T; t++) {
        const float* At = agg + (size_t)t * N * D;
        const float* Wt = W + (size_t)t * D * D;
        for (int kh = 0; kh < 2; kh++) {
            // load W half: rows kh*64..+64, all 128 cols  (2048 float4)
            for (int i = tid; i < 64 * 32; i += 256) {
                int kk = i >> 5, c4 = i & 31;
                ((float4*)Ws)[i] = __ldg((const float4*)(Wt + (size_t)(kh * 64 + kk) * D) + c4);
            }
            // load agg tile: rows m0..m0+63, cols kh*64..+64  (1024 float4)
            for (int i = tid; i < 64 * 16; i += 256) {
                int r = i >> 4, c4 = i & 15;
                float4 v = make_float4(0.f, 0.f, 0.f, 0.f);
                if (m0 + r < N)
                    v = __ldg((const float4*)(At + (size_t)(m0 + r) * D + kh * 64) + c4);
                ((float4*)Xs)[r * 16 + c4] = v;
            }
            __syncthreads();

#pragma unroll
            for (int k0 = 0; k0 < 64; k0 += 4) {
                float4 w0 = ((const float4*)Ws)[(k0 + 0) * 32 + tx];
                float4 w1 = ((const float4*)Ws)[(k0 + 1) * 32 + tx];
                float4 w2 = ((const float4*)Ws)[(k0 + 2) * 32 + tx];
                float4 w3 = ((const float4*)Ws)[(k0 + 3) * 32 + tx];
#pragma unroll
                for (int r = 0; r < 8; r++) {
                    float4 xv = ((const float4*)Xs)[(ty + 8 * r) * 16 + (k0 >> 2)];
                    acc[r].x += xv.x * w0.x + xv.y * w1.x + xv.z * w2.x + xv.w * w3.x;
                    acc[r].y += xv.x * w0.y + xv.y * w1.y + xv.z * w2.y + xv.w * w3.y;
                    acc[r].z += xv.x * w0.z + xv.y * w1.z + xv.z * w2.z + xv.w * w3.z;
                    acc[r].w += xv.x * w0.w + xv.y * w1.w + xv.z * w2.w + xv.w * w3.w;
                }
            }
            __syncthreads();
        }
    }

    // bias: sum over t
    float4 bsum = make_float4(0.f, 0.f, 0.f, 0.f);
    for (int t = 0; t < T; t++) {
        float4 bb = __ldg((const float4*)(b + (size_t)t * D) + tx);
        bsum.x += bb.x; bsum.y += bb.y; bsum.z += bb.z; bsum.w += bb.w;
    }

#pragma unroll
    for (int r = 0; r < 8; r++) {
        int row = m0 + ty + 8 * r;
        if (row < N) {
            float4 v = acc[r];
            v.x += bsum.x; v.y += bsum.y; v.z += bsum.z; v.w += bsum.w;
            ((float4*)(out + (size_t)row * D))[tx] = v;
        }
    }
}

// ---------------------------------------------------------------------------
extern "C" void kernel_launch(void* const* d_in, const int* in_sizes, int n_in,
                              void* d_out, int out_size) {
    const float* x     = (const float*)d_in[0];   // [N, 128]
    const int*   edges = (const int*)d_in[1];     // [T, 2, E]
    const float* W     = (const float*)d_in[2];   // [T, 128, 128]
    const float* b     = (const float*)d_in[3];   // [T, 128]
    float* out = (float*)d_out;                   // [N, 128]

    const int N = in_sizes[0] / D;
    const int T = in_sizes[3] / D;
    const int E = in_sizes[1] / (2 * T);

    float* agg  = nullptr;
    int*   dcnt = nullptr;
    float* dis  = nullptr;
    cudaGetSymbolAddress((void**)(&agg),  g_agg);
    cudaGetSymbolAddress((void**)(&dcnt), g_dcnt);
    cudaGetSymbolAddress((void**)(&dis),  g_dis);

    // 1) zero degree counters
    {
        int n = T * N;
        k_deg_zero<<<(n + 255) / 256, 256>>>(dcnt, n);
    }
    // 2) count
    {
        int total = T * E;
        k_deg_count<<<(total + 255) / 256, 256>>>(edges, dcnt, N, E, T);
    }
    // 3) dis
    {
        int n = T * N;
        k_dis<<<(n + 255) / 256, 256>>>(dcnt, dis, n);
    }
    // 4) agg init with self-loop term
    {
        int n = T * N * 32;
        k_agg_init<<<(n + 255) / 256, 256>>>(x, dis, agg, N, T);
    }
    // 5) edge gather/scatter into agg (8 warps / block of 256)
    {
        int total = T * E;
        int blocks = (total + 7) / 8;
        k_scatter<<<blocks, 256>>>(x, dis, edges, agg, N, E, T);
    }
    // 6) fused GEMM + bias -> out
    {
        k_gemm_out<<<(N + 63) / 64, 256>>>(agg, W, b, out, N, T);
    }
}

// round 9
// speedup vs baseline: 1.0253x; 1.0192x over previous
#include <cuda_runtime.h>
#include <cuda_bf16.h>
#include <cstdint>

// Fixed shapes for this registry entry
#define MAX_N 100000
#define MAX_T 3
#define D 128   // D_IN == D_OUT == 128

// Scratch (allocation-free rule: __device__ globals)
__device__ float g_agg[(size_t)MAX_T * MAX_N * D];   // 153.6 MB aggregated features
__device__ int   g_dcnt[MAX_T * MAX_N];
__device__ float g_dis[MAX_T * MAX_N];

// ---------------------------------------------------------------------------
// 1) zero degree counters
__global__ void k_deg_zero(int* dcnt, int n) {
    int i = blockIdx.x * blockDim.x + threadIdx.x;
    if (i < n) dcnt[i] = 0;
}

// 2) count incoming edges per (relation, dst)
__global__ void k_deg_count(const int* __restrict__ edges, int* __restrict__ dcnt,
                            int N, int E, int T) {
    int i = blockIdx.x * blockDim.x + threadIdx.x;
    int total = T * E;
    if (i >= total) return;
    int t = i / E;
    int e = i - t * E;
    int d = __ldg(edges + (size_t)t * 2 * E + E + e);   // dst
    atomicAdd(dcnt + t * N + d, 1);
}

// 3) dis = rsqrt(count + 1)   (+1 = self loop; always > 0)
__global__ void k_dis(const int* __restrict__ dcnt, float* __restrict__ dis, int n) {
    int i = blockIdx.x * blockDim.x + threadIdx.x;
    if (i < n) dis[i] = rsqrtf((float)(dcnt[i] + 1));
}

// ---------------------------------------------------------------------------
// 4) agg[t][n] = dis[t][n]^2 * x[n]    (self-loop term; also the zero-init)
__global__ void k_agg_init(const float* __restrict__ x, const float* __restrict__ dis,
                           float* __restrict__ agg, int N, int T) {
    int i = blockIdx.x * blockDim.x + threadIdx.x;   // over T * N * 32 float4
    int n32 = N * 32;
    if (i >= T * n32) return;
    int t   = i / n32;
    int rem = i - t * n32;
    int n   = rem >> 5;
    int c4  = rem & 31;
    float ds = __ldg(dis + t * N + n);
    float d2 = ds * ds;
    float4 v = __ldg((const float4*)x + (size_t)n * 32 + c4);
    v.x *= d2; v.y *= d2; v.z *= d2; v.w *= d2;
    ((float4*)agg)[(size_t)i] = v;
}

// ---------------------------------------------------------------------------
// 5) per-edge gather (x, L2-resident) + scatter-add into ONE relation's agg
//    slice (51 MB, L2-resident). One warp per edge; lane 0 loads the edge +
//    norms and broadcasts; each lane moves one float4 of the feature row.
__global__ void k_scatter_t(const float* __restrict__ x, const float* __restrict__ dis_t,
                            const int* __restrict__ srcp, const int* __restrict__ dstp,
                            float* __restrict__ agg_t, int E) {
    int gw   = (blockIdx.x * blockDim.x + threadIdx.x) >> 5;   // edge index
    int lane = threadIdx.x & 31;
    if (gw >= E) return;
    int s = 0, d = 0;
    float norm = 0.f;
    if (lane == 0) {
        s = __ldg(srcp + gw);
        d = __ldg(dstp + gw);
        norm = __ldg(dis_t + s) * __ldg(dis_t + d);
    }
    s    = __shfl_sync(0xffffffffu, s, 0);
    d    = __shfl_sync(0xffffffffu, d, 0);
    norm = __shfl_sync(0xffffffffu, norm, 0);
    float4 v = __ldg((const float4*)x + (size_t)s * 32 + lane);
    float* o = agg_t + (size_t)d * D + lane * 4;
    asm volatile("red.global.add.v4.f32 [%0], {%1, %2, %3, %4};"
                 :: "l"(o), "f"(v.x * norm), "f"(v.y * norm),
                    "f"(v.z * norm), "f"(v.w * norm)
                 : "memory");
}

// ---------------------------------------------------------------------------
// 6) out = sum_t agg[t] @ W[t] + sum_t b[t]
//    block = 256 threads, tile = 64 rows x 128 cols; t-loop and K-halves fused.
__global__ void __launch_bounds__(256, 3)
k_gemm_out(const float* __restrict__ agg, const float* __restrict__ W,
           const float* __restrict__ b, float* __restrict__ out, int N, int T) {
    __shared__ float Ws[64 * 128];   // 32 KB (one K-half of W_t)
    __shared__ float Xs[64 * 64];    // 16 KB (64 rows x 64 k of agg_t)

    const int m0  = blockIdx.x * 64;
    const int tid = threadIdx.x;
    const int tx  = tid & 31;
    const int ty  = tid >> 5;

    float4 acc[8];
#pragma unroll
    for (int r = 0; r < 8; r++) acc[r] = make_float4(0.f, 0.f, 0.f, 0.f);

    for (int t = 0; t < T; t++) {
        const float* At = agg + (size_t)t * N * D;
        const float* Wt = W + (size_t)t * D * D;
        for (int kh = 0; kh < 2; kh++) {
            for (int i = tid; i < 64 * 32; i += 256) {
                int kk = i >> 5, c4 = i & 31;
                ((float4*)Ws)[i] = __ldg((const float4*)(Wt + (size_t)(kh * 64 + kk) * D) + c4);
            }
            for (int i = tid; i < 64 * 16; i += 256) {
                int r = i >> 4, c4 = i & 15;
                float4 v = make_float4(0.f, 0.f, 0.f, 0.f);
                if (m0 + r < N)
                    v = __ldg((const float4*)(At + (size_t)(m0 + r) * D + kh * 64) + c4);
                ((float4*)Xs)[r * 16 + c4] = v;
            }
            __syncthreads();

#pragma unroll
            for (int k0 = 0; k0 < 64; k0 += 4) {
                float4 w0 = ((const float4*)Ws)[(k0 + 0) * 32 + tx];
                float4 w1 = ((const float4*)Ws)[(k0 + 1) * 32 + tx];
                float4 w2 = ((const float4*)Ws)[(k0 + 2) * 32 + tx];
                float4 w3 = ((const float4*)Ws)[(k0 + 3) * 32 + tx];
#pragma unroll
                for (int r = 0; r < 8; r++) {
                    float4 xv = ((const float4*)Xs)[(ty + 8 * r) * 16 + (k0 >> 2)];
                    acc[r].x += xv.x * w0.x + xv.y * w1.x + xv.z * w2.x + xv.w * w3.x;
                    acc[r].y += xv.x * w0.y + xv.y * w1.y + xv.z * w2.y + xv.w * w3.y;
                    acc[r].z += xv.x * w0.z + xv.y * w1.z + xv.z * w2.z + xv.w * w3.z;
                    acc[r].w += xv.x * w0.w + xv.y * w1.w + xv.z * w2.w + xv.w * w3.w;
                }
            }
            __syncthreads();
        }
    }

    float4 bsum = make_float4(0.f, 0.f, 0.f, 0.f);
    for (int t = 0; t < T; t++) {
        float4 bb = __ldg((const float4*)(b + (size_t)t * D) + tx);
        bsum.x += bb.x; bsum.y += bb.y; bsum.z += bb.z; bsum.w += bb.w;
    }

#pragma unroll
    for (int r = 0; r < 8; r++) {
        int row = m0 + ty + 8 * r;
        if (row < N) {
            float4 v = acc[r];
            v.x += bsum.x; v.y += bsum.y; v.z += bsum.z; v.w += bsum.w;
            ((float4*)(out + (size_t)row * D))[tx] = v;
        }
    }
}

// ---------------------------------------------------------------------------
extern "C" void kernel_launch(void* const* d_in, const int* in_sizes, int n_in,
                              void* d_out, int out_size) {
    const float* x     = (const float*)d_in[0];   // [N, 128]
    const int*   edges = (const int*)d_in[1];     // [T, 2, E]
    const float* W     = (const float*)d_in[2];   // [T, 128, 128]
    const float* b     = (const float*)d_in[3];   // [T, 128]
    float* out = (float*)d_out;                   // [N, 128]

    const int N = in_sizes[0] / D;
    const int T = in_sizes[3] / D;
    const int E = in_sizes[1] / (2 * T);

    float* agg  = nullptr;
    int*   dcnt = nullptr;
    float* dis  = nullptr;
    cudaGetSymbolAddress((void**)(&agg),  g_agg);
    cudaGetSymbolAddress((void**)(&dcnt), g_dcnt);
    cudaGetSymbolAddress((void**)(&dis),  g_dis);

    // 1) zero degree counters
    {
        int n = T * N;
        k_deg_zero<<<(n + 255) / 256, 256>>>(dcnt, n);
    }
    // 2) count
    {
        int total = T * E;
        k_deg_count<<<(total + 255) / 256, 256>>>(edges, dcnt, N, E, T);
    }
    // 3) dis
    {
        int n = T * N;
        k_dis<<<(n + 255) / 256, 256>>>(dcnt, dis, n);
    }
    // 4) agg init with self-loop term
    {
        int n = T * N * 32;
        k_agg_init<<<(n + 255) / 256, 256>>>(x, dis, agg, N, T);
    }
    // 5) edge gather/scatter, ONE RELATION PER LAUNCH (51+51 MB working set,
    //    L2-resident; x stays hot across launches since L2 persists)
    for (int t = 0; t < T; t++) {
        const int* srcp = edges + (size_t)t * 2 * E;
        const int* dstp = srcp + E;
        int blocks = (E + 7) / 8;   // 8 warps / 256-thread block
        k_scatter_t<<<blocks, 256>>>(x, dis + (size_t)t * N, srcp, dstp,
                                     agg + (size_t)t * N * D, E);
    }
    // 6) fused GEMM + bias -> out
    {
        k_gemm_out<<<(N + 63) / 64, 256>>>(agg, W, b, out, N, T);
    }
}

// round 11
// speedup vs baseline: 1.3528x; 1.3194x over previous
#include <cuda_runtime.h>
#include <cuda_bf16.h>
#include <cstdint>

// Fixed shapes for this registry entry
#define MAX_N 100000
#define MAX_T 3
#define D 128
#define MAX_E 800000

// Scratch (allocation-free rule: __device__ globals)
__device__ float g_agg[(size_t)MAX_T * MAX_N * D];      // 153.6 MB aggregated features
__device__ int   g_dcnt[MAX_T * MAX_N];                 // in-degree per (t, dst)
__device__ float g_dis[MAX_T * MAX_N];                  // rsqrt(deg+1)
__device__ int   g_offs[MAX_T * MAX_N];                 // CSR row offsets (exclusive scan)
__device__ int   g_cur[MAX_T * MAX_N];                  // fill cursors
__device__ int   g_slist[MAX_T * MAX_E];                // bucketed src indices
__device__ int   g_bsum[512];                           // block sums for scan
__device__ int   g_bexcl[512];                          // exclusive-scanned block sums

// ---------------------------------------------------------------------------
__global__ void k_deg_zero(int* dcnt, int n) {
    int i = blockIdx.x * blockDim.x + threadIdx.x;
    if (i < n) dcnt[i] = 0;
}

__global__ void k_deg_count(const int* __restrict__ edges, int* __restrict__ dcnt,
                            int N, int E, int T) {
    int i = blockIdx.x * blockDim.x + threadIdx.x;
    int total = T * E;
    if (i >= total) return;
    int t = i / E;
    int e = i - t * E;
    int d = __ldg(edges + (size_t)t * 2 * E + E + e);   // dst
    atomicAdd(dcnt + t * N + d, 1);
}

__global__ void k_dis(const int* __restrict__ dcnt, float* __restrict__ dis, int n) {
    int i = blockIdx.x * blockDim.x + threadIdx.x;
    if (i < n) dis[i] = rsqrtf((float)(dcnt[i] + 1));
}

// ---------------------------------------------------------------------------
// Exclusive scan of dcnt -> offs.  1024 elements / block (256 thr x 4).
__global__ void k_scan_reduce(const int* __restrict__ dcnt, int* __restrict__ bsum, int n) {
    __shared__ int sh[256];
    int tid = threadIdx.x;
    int base = blockIdx.x * 1024 + tid * 4;
    int s = 0;
#pragma unroll
    for (int j = 0; j < 4; j++) if (base + j < n) s += dcnt[base + j];
    sh[tid] = s;
    __syncthreads();
    for (int off = 128; off > 0; off >>= 1) {
        if (tid < off) sh[tid] += sh[tid + off];
        __syncthreads();
    }
    if (tid == 0) bsum[blockIdx.x] = sh[0];
}

__global__ void k_scan_bsum(const int* __restrict__ bsum, int* __restrict__ bexcl, int nblk) {
    __shared__ int sh[512];
    int tid = threadIdx.x;
    int v = (tid < nblk) ? bsum[tid] : 0;
    sh[tid] = v;
    __syncthreads();
    for (int off = 1; off < 512; off <<= 1) {
        int t = 0;
        if (tid >= off) t = sh[tid - off];
        __syncthreads();
        sh[tid] += t;
        __syncthreads();
    }
    if (tid < nblk) bexcl[tid] = sh[tid] - v;
}

__global__ void k_scan_final(const int* __restrict__ dcnt, const int* __restrict__ bexcl,
                             int* __restrict__ offs, int* __restrict__ cur, int n) {
    __shared__ int sh[256];
    int tid = threadIdx.x;
    int base = blockIdx.x * 1024 + tid * 4;
    int v[4];
#pragma unroll
    for (int j = 0; j < 4; j++) v[j] = (base + j < n) ? dcnt[base + j] : 0;
    int tsum = v[0] + v[1] + v[2] + v[3];
    sh[tid] = tsum;
    __syncthreads();
    for (int off = 1; off < 256; off <<= 1) {
        int t = 0;
        if (tid >= off) t = sh[tid - off];
        __syncthreads();
        sh[tid] += t;
        __syncthreads();
    }
    int excl = sh[tid] - tsum + bexcl[blockIdx.x];
#pragma unroll
    for (int j = 0; j < 4; j++) {
        if (base + j < n) { offs[base + j] = excl; cur[base + j] = excl; }
        excl += v[j];
    }
}

// ---------------------------------------------------------------------------
// Bucket each edge's src into its (t, dst) slot.
__global__ void k_fill(const int* __restrict__ edges, int* __restrict__ cur,
                       int* __restrict__ slist, int N, int E, int T) {
    int i = blockIdx.x * blockDim.x + threadIdx.x;
    int total = T * E;
    if (i >= total) return;
    int t = i / E;
    int e = i - t * E;
    const int* srcp = edges + (size_t)t * 2 * E;
    int s = __ldg(srcp + e);
    int d = __ldg(srcp + E + e);
    int pos = atomicAdd(cur + t * N + d, 1);
    slist[pos] = s;
}

// ---------------------------------------------------------------------------
// One warp per (t, dst): agg[t][d] = dis[d] * ( dis[d]*x[d] + sum_s dis[s]*x[s] )
// No atomics: registers accumulate, one plain 512B store.
__global__ void k_gather(const float* __restrict__ x, const float* __restrict__ dis,
                         const int* __restrict__ offs, const int* __restrict__ dcnt,
                         const int* __restrict__ slist, float* __restrict__ agg,
                         int N, int T) {
    int gw   = (blockIdx.x * blockDim.x + threadIdx.x) >> 5;   // tn index
    int lane = threadIdx.x & 31;
    int total = T * N;
    if (gw >= total) return;
    int t = gw / N;
    int d = gw - t * N;

    float dd  = __ldg(dis + gw);
    int   off = __ldg(offs + gw);
    int   deg = __ldg(dcnt + gw);

    float4 acc = __ldg((const float4*)x + (size_t)d * 32 + lane);
    acc.x *= dd; acc.y *= dd; acc.z *= dd; acc.w *= dd;   // self-loop (pre-scale)

    for (int base = 0; base < deg; base += 32) {
        int   myS = 0;
        float myW = 0.f;
        int m = deg - base; if (m > 32) m = 32;
        if (lane < m) {
            myS = __ldg(slist + off + base + lane);
            myW = __ldg(dis + t * N + myS);
        }
        for (int j = 0; j < m; j++) {
            int   s = __shfl_sync(0xffffffffu, myS, j);
            float w = __shfl_sync(0xffffffffu, myW, j);
            float4 v = __ldg((const float4*)x + (size_t)s * 32 + lane);
            acc.x += w * v.x; acc.y += w * v.y; acc.z += w * v.z; acc.w += w * v.w;
        }
    }
    acc.x *= dd; acc.y *= dd; acc.z *= dd; acc.w *= dd;
    ((float4*)agg)[(size_t)gw * 32 + lane] = acc;
}

// ---------------------------------------------------------------------------
// out = sum_t agg[t] @ W[t] + sum_t b[t]
__global__ void __launch_bounds__(256, 3)
k_gemm_out(const float* __restrict__ agg, const float* __restrict__ W,
           const float* __restrict__ b, float* __restrict__ out, int N, int T) {
    __shared__ float Ws[64 * 128];
    __shared__ float Xs[64 * 64];

    const int m0  = blockIdx.x * 64;
    const int tid = threadIdx.x;
    const int tx  = tid & 31;
    const int ty  = tid >> 5;

    float4 acc[8];
#pragma unroll
    for (int r = 0; r < 8; r++) acc[r] = make_float4(0.f, 0.f, 0.f, 0.f);

    for (int t = 0; t < T; t++) {
        const float* At = agg + (size_t)t * N * D;
        const float* Wt = W + (size_t)t * D * D;
        for (int kh = 0; kh < 2; kh++) {
            for (int i = tid; i < 64 * 32; i += 256) {
                int kk = i >> 5, c4 = i & 31;
                ((float4*)Ws)[i] = __ldg((const float4*)(Wt + (size_t)(kh * 64 + kk) * D) + c4);
            }
            for (int i = tid; i < 64 * 16; i += 256) {
                int r = i >> 4, c4 = i & 15;
                float4 v = make_float4(0.f, 0.f, 0.f, 0.f);
                if (m0 + r < N)
                    v = __ldg((const float4*)(At + (size_t)(m0 + r) * D + kh * 64) + c4);
                ((float4*)Xs)[r * 16 + c4] = v;
            }
            __syncthreads();

#pragma unroll
            for (int k0 = 0; k0 < 64; k0 += 4) {
                float4 w0 = ((const float4*)Ws)[(k0 + 0) * 32 + tx];
                float4 w1 = ((const float4*)Ws)[(k0 + 1) * 32 + tx];
                float4 w2 = ((const float4*)Ws)[(k0 + 2) * 32 + tx];
                float4 w3 = ((const float4*)Ws)[(k0 + 3) * 32 + tx];
#pragma unroll
                for (int r = 0; r < 8; r++) {
                    float4 xv = ((const float4*)Xs)[(ty + 8 * r) * 16 + (k0 >> 2)];
                    acc[r].x += xv.x * w0.x + xv.y * w1.x + xv.z * w2.x + xv.w * w3.x;
                    acc[r].y += xv.x * w0.y + xv.y * w1.y + xv.z * w2.y + xv.w * w3.y;
                    acc[r].z += xv.x * w0.z + xv.y * w1.z + xv.z * w2.z + xv.w * w3.z;
                    acc[r].w += xv.x * w0.w + xv.y * w1.w + xv.z * w2.w + xv.w * w3.w;
                }
            }
            __syncthreads();
        }
    }

    float4 bsum = make_float4(0.f, 0.f, 0.f, 0.f);
    for (int t = 0; t < T; t++) {
        float4 bb = __ldg((const float4*)(b + (size_t)t * D) + tx);
        bsum.x += bb.x; bsum.y += bb.y; bsum.z += bb.z; bsum.w += bb.w;
    }

#pragma unroll
    for (int r = 0; r < 8; r++) {
        int row = m0 + ty + 8 * r;
        if (row < N) {
            float4 v = acc[r];
            v.x += bsum.x; v.y += bsum.y; v.z += bsum.z; v.w += bsum.w;
            ((float4*)(out + (size_t)row * D))[tx] = v;
        }
    }
}

// ---------------------------------------------------------------------------
extern "C" void kernel_launch(void* const* d_in, const int* in_sizes, int n_in,
                              void* d_out, int out_size) {
    const float* x     = (const float*)d_in[0];   // [N, 128]
    const int*   edges = (const int*)d_in[1];     // [T, 2, E]
    const float* W     = (const float*)d_in[2];   // [T, 128, 128]
    const float* b     = (const float*)d_in[3];   // [T, 128]
    float* out = (float*)d_out;                   // [N, 128]

    const int N = in_sizes[0] / D;
    const int T = in_sizes[3] / D;
    const int E = in_sizes[1] / (2 * T);

    float *agg = nullptr, *dis = nullptr;
    int *dcnt = nullptr, *offs = nullptr, *cur = nullptr, *slist = nullptr;
    int *bsum = nullptr, *bexcl = nullptr;
    cudaGetSymbolAddress((void**)(&agg),   g_agg);
    cudaGetSymbolAddress((void**)(&dcnt),  g_dcnt);
    cudaGetSymbolAddress((void**)(&dis),   g_dis);
    cudaGetSymbolAddress((void**)(&offs),  g_offs);
    cudaGetSymbolAddress((void**)(&cur),   g_cur);
    cudaGetSymbolAddress((void**)(&slist), g_slist);
    cudaGetSymbolAddress((void**)(&bsum),  g_bsum);
    cudaGetSymbolAddress((void**)(&bexcl), g_bexcl);

    const int n    = T * N;                 // 300000
    const int nblk = (n + 1023) / 1024;     // <= 512

    // 1) degree counting
    k_deg_zero<<<(n + 255) / 256, 256>>>(dcnt, n);
    {
        int total = T * E;
        k_deg_count<<<(total + 255) / 256, 256>>>(edges, dcnt, N, E, T);
    }
    // 2) dis = rsqrt(deg+1)
    k_dis<<<(n + 255) / 256, 256>>>(dcnt, dis, n);
    // 3) exclusive scan dcnt -> offs (and cursor copy)
    k_scan_reduce<<<nblk, 256>>>(dcnt, bsum, n);
    k_scan_bsum<<<1, 512>>>(bsum, bexcl, nblk);
    k_scan_final<<<nblk, 256>>>(dcnt, bexcl, offs, cur, n);
    // 4) bucket srcs per (t, dst)
    {
        int total = T * E;
        k_fill<<<(total + 255) / 256, 256>>>(edges, cur, slist, N, E, T);
    }
    // 5) gather-aggregate (no atomics), one warp per (t, dst)
    {
        int warps = n;
        int blocks = (warps + 7) / 8;
        k_gather<<<blocks, 256>>>(x, dis, offs, dcnt, slist, agg, N, T);
    }
    // 6) fused GEMM + bias -> out
    k_gemm_out<<<(N + 63) / 64, 256>>>(agg, W, b, out, N, T);
}

// round 13
// speedup vs baseline: 2.0237x; 1.4959x over previous
#include <cuda_runtime.h>
#include <cuda_bf16.h>
#include <cstdint>

// Fixed shapes for this registry entry
#define MAX_N 100000
#define MAX_T 3
#define D 128
#define MAX_E 800000

// Scratch (allocation-free rule: __device__ globals)
__device__ float g_agg[(size_t)MAX_T * MAX_N * D];      // 153.6 MB aggregated features
__device__ int   g_dcnt[MAX_T * MAX_N];                 // in-degree per (t, dst)
__device__ float g_dis[MAX_T * MAX_N];                  // rsqrt(deg+1)
__device__ int   g_offs[MAX_T * MAX_N];                 // CSR row offsets
__device__ int   g_cur[MAX_T * MAX_N];                  // fill cursors
__device__ int   g_slist[MAX_T * MAX_E];                // bucketed src indices
__device__ int   g_bsum[512];
__device__ int   g_bexcl[512];

// ---------------------------------------------------------------------------
__global__ void k_deg_zero(int* dcnt, int n) {
    int i = blockIdx.x * blockDim.x + threadIdx.x;
    if (i < n) dcnt[i] = 0;
}

__global__ void k_deg_count(const int* __restrict__ edges, int* __restrict__ dcnt,
                            int N, int E, int T) {
    int i = blockIdx.x * blockDim.x + threadIdx.x;
    int total = T * E;
    if (i >= total) return;
    int t = i / E;
    int e = i - t * E;
    int d = __ldg(edges + (size_t)t * 2 * E + E + e);   // dst
    atomicAdd(dcnt + t * N + d, 1);
}

__global__ void k_dis(const int* __restrict__ dcnt, float* __restrict__ dis, int n) {
    int i = blockIdx.x * blockDim.x + threadIdx.x;
    if (i < n) dis[i] = rsqrtf((float)(dcnt[i] + 1));
}

// ---------------------------------------------------------------------------
// Exclusive scan of dcnt -> offs.  1024 elements / block.
__global__ void k_scan_reduce(const int* __restrict__ dcnt, int* __restrict__ bsum, int n) {
    __shared__ int sh[256];
    int tid = threadIdx.x;
    int base = blockIdx.x * 1024 + tid * 4;
    int s = 0;
#pragma unroll
    for (int j = 0; j < 4; j++) if (base + j < n) s += dcnt[base + j];
    sh[tid] = s;
    __syncthreads();
    for (int off = 128; off > 0; off >>= 1) {
        if (tid < off) sh[tid] += sh[tid + off];
        __syncthreads();
    }
    if (tid == 0) bsum[blockIdx.x] = sh[0];
}

__global__ void k_scan_bsum(const int* __restrict__ bsum, int* __restrict__ bexcl, int nblk) {
    __shared__ int sh[512];
    int tid = threadIdx.x;
    int v = (tid < nblk) ? bsum[tid] : 0;
    sh[tid] = v;
    __syncthreads();
    for (int off = 1; off < 512; off <<= 1) {
        int t = 0;
        if (tid >= off) t = sh[tid - off];
        __syncthreads();
        sh[tid] += t;
        __syncthreads();
    }
    if (tid < nblk) bexcl[tid] = sh[tid] - v;
}

__global__ void k_scan_final(const int* __restrict__ dcnt, const int* __restrict__ bexcl,
                             int* __restrict__ offs, int* __restrict__ cur, int n) {
    __shared__ int sh[256];
    int tid = threadIdx.x;
    int base = blockIdx.x * 1024 + tid * 4;
    int v[4];
#pragma unroll
    for (int j = 0; j < 4; j++) v[j] = (base + j < n) ? dcnt[base + j] : 0;
    int tsum = v[0] + v[1] + v[2] + v[3];
    sh[tid] = tsum;
    __syncthreads();
    for (int off = 1; off < 256; off <<= 1) {
        int t = 0;
        if (tid >= off) t = sh[tid - off];
        __syncthreads();
        sh[tid] += t;
        __syncthreads();
    }
    int excl = sh[tid] - tsum + bexcl[blockIdx.x];
#pragma unroll
    for (int j = 0; j < 4; j++) {
        if (base + j < n) { offs[base + j] = excl; cur[base + j] = excl; }
        excl += v[j];
    }
}

// ---------------------------------------------------------------------------
__global__ void k_fill(const int* __restrict__ edges, int* __restrict__ cur,
                       int* __restrict__ slist, int N, int E, int T) {
    int i = blockIdx.x * blockDim.x + threadIdx.x;
    int total = T * E;
    if (i >= total) return;
    int t = i / E;
    int e = i - t * E;
    const int* srcp = edges + (size_t)t * 2 * E;
    int s = __ldg(srcp + e);
    int d = __ldg(srcp + E + e);
    int pos = atomicAdd(cur + t * N + d, 1);
    slist[pos] = s;
}

// ---------------------------------------------------------------------------
// One warp per (t, dst): agg[t][d] = dis[d] * ( dis[d]*x[d] + sum_s dis[s]*x[s] )
__global__ void k_gather(const float* __restrict__ x, const float* __restrict__ dis,
                         const int* __restrict__ offs, const int* __restrict__ dcnt,
                         const int* __restrict__ slist, float* __restrict__ agg,
                         int N, int T) {
    int gw   = (blockIdx.x * blockDim.x + threadIdx.x) >> 5;
    int lane = threadIdx.x & 31;
    int total = T * N;
    if (gw >= total) return;
    int t = gw / N;
    int d = gw - t * N;

    float dd  = __ldg(dis + gw);
    int   off = __ldg(offs + gw);
    int   deg = __ldg(dcnt + gw);

    float4 acc = __ldg((const float4*)x + (size_t)d * 32 + lane);
    acc.x *= dd; acc.y *= dd; acc.z *= dd; acc.w *= dd;

    for (int base = 0; base < deg; base += 32) {
        int   myS = 0;
        float myW = 0.f;
        int m = deg - base; if (m > 32) m = 32;
        if (lane < m) {
            myS = __ldg(slist + off + base + lane);
            myW = __ldg(dis + t * N + myS);
        }
        for (int j = 0; j < m; j++) {
            int   s = __shfl_sync(0xffffffffu, myS, j);
            float w = __shfl_sync(0xffffffffu, myW, j);
            float4 v = __ldg((const float4*)x + (size_t)s * 32 + lane);
            acc.x += w * v.x; acc.y += w * v.y; acc.z += w * v.z; acc.w += w * v.w;
        }
    }
    acc.x *= dd; acc.y *= dd; acc.z *= dd; acc.w *= dd;
    ((float4*)agg)[(size_t)gw * 32 + lane] = acc;
}

// ---------------------------------------------------------------------------
// Split-bf16 tensor-core GEMM: out = sum_t agg[t] @ W[t] + sum_t b[t]
// A*W ~= Ahi*Whi + Ahi*Wlo + Alo*Whi  (drops Alo*Wlo ~ 2^-16 relative).
// Block tile 128x128, k-tile 32, 8 warps (4 m x 2 n), mma.m16n8k16 bf16/f32.
#define LDA 40    // bf16 elems per A smem row (32 data + 8 pad -> conflict-free)
#define LDW 136   // bf16 elems per W smem row (128 data + 8 pad)

__device__ __forceinline__ void mma_bf16(float* c, const uint32_t* a, const uint32_t* b) {
    asm volatile(
        "mma.sync.aligned.m16n8k16.row.col.f32.bf16.bf16.f32 "
        "{%0,%1,%2,%3}, {%4,%5,%6,%7}, {%8,%9}, {%0,%1,%2,%3};"
        : "+f"(c[0]), "+f"(c[1]), "+f"(c[2]), "+f"(c[3])
        : "r"(a[0]), "r"(a[1]), "r"(a[2]), "r"(a[3]), "r"(b[0]), "r"(b[1]));
}

__device__ __forceinline__ uint32_t smem_u32(const void* p) {
    return (uint32_t)__cvta_generic_to_shared(p);
}

__device__ __forceinline__ void ldsm_x4(uint32_t* r, uint32_t addr) {
    asm volatile("ldmatrix.sync.aligned.m8n8.x4.shared.b16 {%0,%1,%2,%3}, [%4];"
                 : "=r"(r[0]), "=r"(r[1]), "=r"(r[2]), "=r"(r[3]) : "r"(addr));
}

__device__ __forceinline__ void ldsm_x4_t(uint32_t* r, uint32_t addr) {
    asm volatile("ldmatrix.sync.aligned.m8n8.x4.trans.shared.b16 {%0,%1,%2,%3}, [%4];"
                 : "=r"(r[0]), "=r"(r[1]), "=r"(r[2]), "=r"(r[3]) : "r"(addr));
}

__device__ __forceinline__ void split_pair(float a, float b,
                                           __nv_bfloat162* hi, __nv_bfloat162* lo) {
    __nv_bfloat16 ha = __float2bfloat16(a);
    __nv_bfloat16 hb = __float2bfloat16(b);
    __nv_bfloat16 la = __float2bfloat16(a - __bfloat162float(ha));
    __nv_bfloat16 lb = __float2bfloat16(b - __bfloat162float(hb));
    *hi = __halves2bfloat162(ha, hb);
    *lo = __halves2bfloat162(la, lb);
}

__global__ void __launch_bounds__(256, 2)
k_gemm_mma(const float* __restrict__ agg, const float* __restrict__ W,
           const float* __restrict__ b, float* __restrict__ out, int N, int T) {
    __shared__ __nv_bfloat16 sAhi[128 * LDA];
    __shared__ __nv_bfloat16 sAlo[128 * LDA];
    __shared__ __nv_bfloat16 sWhi[32 * LDW];
    __shared__ __nv_bfloat16 sWlo[32 * LDW];
    __shared__ float bs[128];

    const int tid  = threadIdx.x;
    const int wid  = tid >> 5;
    const int lane = tid & 31;
    const int wm   = wid & 3;        // warp row (32 rows each)
    const int wn   = wid >> 2;       // warp col (64 cols each)
    const int g    = lane >> 2;      // mma group id
    const int tg   = lane & 3;       // thread-in-group
    const int R0   = blockIdx.x * 128;

    if (tid < 128) {
        float s = 0.f;
        for (int t = 0; t < T; t++) s += __ldg(b + t * 128 + tid);
        bs[tid] = s;
    }

    float acc[2][8][4];
#pragma unroll
    for (int mb = 0; mb < 2; mb++)
#pragma unroll
        for (int nf = 0; nf < 8; nf++)
#pragma unroll
            for (int j = 0; j < 4; j++) acc[mb][nf][j] = 0.f;

    // ldmatrix lane-address components (per the m8n8 x4 convention)
    const int lm   = lane >> 3;          // matrix id 0..3
    const int lr   = lane & 7;           // row within matrix
    const int a_r  = (lm & 1) * 8 + lr;  // A: row offset within 16
    const int a_c8 = (lm >> 1) * 8;      // A: col offset (k) 0/8
    const int w_kr = (lm & 1) * 8 + lr;  // W: k-row within 16
    const int w_n8 = (lm >> 1) * 8;      // W: n offset 0/8

    for (int t = 0; t < T; t++) {
        const float* At = agg + (size_t)t * N * 128;
        const float* Wt = W + (size_t)t * 128 * 128;
        for (int kt = 0; kt < 4; kt++) {
            __syncthreads();
            // stage A tile 128x32 fp32 -> hi/lo bf16
#pragma unroll
            for (int it = 0; it < 4; it++) {
                int idx = tid + it * 256;          // 0..1023
                int row = idx >> 3, c4 = idx & 7;  // 8 float4 per row
                float4 v = make_float4(0.f, 0.f, 0.f, 0.f);
                if (R0 + row < N)
                    v = __ldg((const float4*)(At + (size_t)(R0 + row) * 128 + kt * 32) + c4);
                __nv_bfloat162 h0, l0, h1, l1;
                split_pair(v.x, v.y, &h0, &l0);
                split_pair(v.z, v.w, &h1, &l1);
                __nv_bfloat162* ph = (__nv_bfloat162*)&sAhi[row * LDA + c4 * 4];
                __nv_bfloat162* pl = (__nv_bfloat162*)&sAlo[row * LDA + c4 * 4];
                ph[0] = h0; ph[1] = h1;
                pl[0] = l0; pl[1] = l1;
            }
            // stage W tile 32x128 fp32 -> hi/lo bf16
#pragma unroll
            for (int it = 0; it < 4; it++) {
                int idx = tid + it * 256;           // 0..1023
                int row = idx >> 5, c4 = idx & 31;  // 32 float4 per row
                float4 v = __ldg((const float4*)(Wt + (size_t)(kt * 32 + row) * 128) + c4);
                __nv_bfloat162 h0, l0, h1, l1;
                split_pair(v.x, v.y, &h0, &l0);
                split_pair(v.z, v.w, &h1, &l1);
                __nv_bfloat162* ph = (__nv_bfloat162*)&sWhi[row * LDW + c4 * 4];
                __nv_bfloat162* pl = (__nv_bfloat162*)&sWlo[row * LDW + c4 * 4];
                ph[0] = h0; ph[1] = h1;
                pl[0] = l0; pl[1] = l1;
            }
            __syncthreads();

#pragma unroll
            for (int ks = 0; ks < 2; ks++) {
                // A fragments (2 m-blocks, hi & lo)
                uint32_t ahi[2][4], alo[2][4];
#pragma unroll
                for (int mb = 0; mb < 2; mb++) {
                    int row = wm * 32 + mb * 16 + a_r;
                    int col = ks * 16 + a_c8;
                    ldsm_x4(ahi[mb], smem_u32(&sAhi[row * LDA + col]));
                    ldsm_x4(alo[mb], smem_u32(&sAlo[row * LDA + col]));
                }
                // B fragments per n16 pair, mma immediately (keeps regs low)
#pragma unroll
                for (int np = 0; np < 4; np++) {
                    int krow = ks * 16 + w_kr;
                    int ncol = wn * 64 + np * 16 + w_n8;
                    uint32_t bh[4], bl[4];
                    ldsm_x4_t(bh, smem_u32(&sWhi[krow * LDW + ncol]));
                    ldsm_x4_t(bl, smem_u32(&sWlo[krow * LDW + ncol]));
#pragma unroll
                    for (int mb = 0; mb < 2; mb++) {
                        mma_bf16(acc[mb][np * 2],     ahi[mb], bh);
                        mma_bf16(acc[mb][np * 2],     ahi[mb], bl);
                        mma_bf16(acc[mb][np * 2],     alo[mb], bh);
                        mma_bf16(acc[mb][np * 2 + 1], ahi[mb], bh + 2);
                        mma_bf16(acc[mb][np * 2 + 1], ahi[mb], bl + 2);
                        mma_bf16(acc[mb][np * 2 + 1], alo[mb], bh + 2);
                    }
                }
            }
        }
    }

    // epilogue: bias + store (float2 per half-fragment)
#pragma unroll
    for (int mb = 0; mb < 2; mb++) {
        int row0 = R0 + wm * 32 + mb * 16 + g;
        int row1 = row0 + 8;
#pragma unroll
        for (int nf = 0; nf < 8; nf++) {
            int col = wn * 64 + nf * 8 + tg * 2;
            float bx = bs[col], by = bs[col + 1];
            if (row0 < N) {
                float2 v0 = make_float2(acc[mb][nf][0] + bx, acc[mb][nf][1] + by);
                *(float2*)(out + (size_t)row0 * 128 + col) = v0;
            }
            if (row1 < N) {
                float2 v1 = make_float2(acc[mb][nf][2] + bx, acc[mb][nf][3] + by);
                *(float2*)(out + (size_t)row1 * 128 + col) = v1;
            }
        }
    }
}

// ---------------------------------------------------------------------------
extern "C" void kernel_launch(void* const* d_in, const int* in_sizes, int n_in,
                              void* d_out, int out_size) {
    const float* x     = (const float*)d_in[0];   // [N, 128]
    const int*   edges = (const int*)d_in[1];     // [T, 2, E]
    const float* W     = (const float*)d_in[2];   // [T, 128, 128]
    const float* b     = (const float*)d_in[3];   // [T, 128]
    float* out = (float*)d_out;                   // [N, 128]

    const int N = in_sizes[0] / D;
    const int T = in_sizes[3] / D;
    const int E = in_sizes[1] / (2 * T);

    float *agg = nullptr, *dis = nullptr;
    int *dcnt = nullptr, *offs = nullptr, *cur = nullptr, *slist = nullptr;
    int *bsum = nullptr, *bexcl = nullptr;
    cudaGetSymbolAddress((void**)(&agg),   g_agg);
    cudaGetSymbolAddress((void**)(&dcnt),  g_dcnt);
    cudaGetSymbolAddress((void**)(&dis),   g_dis);
    cudaGetSymbolAddress((void**)(&offs),  g_offs);
    cudaGetSymbolAddress((void**)(&cur),   g_cur);
    cudaGetSymbolAddress((void**)(&slist), g_slist);
    cudaGetSymbolAddress((void**)(&bsum),  g_bsum);
    cudaGetSymbolAddress((void**)(&bexcl), g_bexcl);

    const int n    = T * N;
    const int nblk = (n + 1023) / 1024;

    k_deg_zero<<<(n + 255) / 256, 256>>>(dcnt, n);
    {
        int total = T * E;
        k_deg_count<<<(total + 255) / 256, 256>>>(edges, dcnt, N, E, T);
    }
    k_dis<<<(n + 255) / 256, 256>>>(dcnt, dis, n);
    k_scan_reduce<<<nblk, 256>>>(dcnt, bsum, n);
    k_scan_bsum<<<1, 512>>>(bsum, bexcl, nblk);
    k_scan_final<<<nblk, 256>>>(dcnt, bexcl, offs, cur, n);
    {
        int total = T * E;
        k_fill<<<(total + 255) / 256, 256>>>(edges, cur, slist, N, E, T);
    }
    {
        int warps = n;
        int blocks = (warps + 7) / 8;
        k_gather<<<blocks, 256>>>(x, dis, offs, dcnt, slist, agg, N, T);
    }
    // split-bf16 tensor-core GEMM + bias
    k_gemm_mma<<<(N + 127) / 128, 256>>>(agg, W, b, out, N, T);
}